// round 11
// baseline (speedup 1.0000x reference)
#include <cuda_runtime.h>
#include <cuda_fp16.h>
#include <cstdint>
#include <cstddef>

// ---------------------------------------------------------------------------
// EP free-phase relaxation. Persistent single-pass fp16 mma.sync kernel,
// 512 threads/CTA (16 warps 4x4), BK=128 DEPTH=2 pipeline, per-m-half
// dataflow flags (two independent 72-CTA pipelines), weight prefetch before
// flag waits, split-K rebalance (G2 computes 2 stages of G1's s0@W0 term).
//   G0 (16 CTAs): s0' = rho(s1 W0^T + b0)                      16 stages
//   G1 (64 CTAs): s1' = rho(s2 W1^T + s0 W0[k<256] + c1p + b1) 18 stages
//   G2 (64 CTAs): c1p = s0 W0[k 256:512] (2 st) then s2' (16)  18 stages
// C2 = data@W2^T + b2 split-K over 128 CTAs (c2 + c2p, folded at t=1).
// ---------------------------------------------------------------------------

#define BATCH 256
#define D0 512
#define D1 2048
#define D2 2048
#define DIN 4096
#define T_STEPS 20

#define BM 128
#define BN 64
#define BK 128
#define DEPTH 2
#define THREADS 512

#define ROW_BYTES 272                    // 128 halves (256B) + 16B pad
#define A_MAT (128 * ROW_BYTES)          // 34816
#define B_MAT (64 * ROW_BYTES)           // 17408
#define OFF_A 0
#define OFF_B (A_MAT)
#define STAGE_BYTES (A_MAT + B_MAT)      // 52224
#define DSMEM_BYTES (DEPTH * STAGE_BYTES) // 104448

// --------------------------- device scratch --------------------------------
__device__ __half g_hW0[D0 * D1];
__device__ __half g_hW1[D1 * D2];
__device__ __half g_hW0T[D1 * D0];
__device__ __half g_hW1T[D2 * D1];
__device__ __half g_hW2[D2 * DIN];
__device__ __half g_hd[BATCH * DIN];
__device__ __half g_hs0[2][BATCH * D0];
__device__ __half g_hs1[2][BATCH * D1];
__device__ __half g_hs2[2][BATCH * D2];
__device__ float g_c2[BATCH * D2];
__device__ float g_c2p[BATCH * D2];
__device__ float g_c1p[2][BATCH * D1];        // split-K partial (parity)
__device__ int g_done0[2], g_done1[2], g_done2[2];  // per-m-half counters
__device__ int g_part[2];                     // per-m-half partial counters

// ------------------------------ PTX helpers --------------------------------
__device__ __forceinline__ uint32_t smem_u32(const void* p) {
    uint32_t a;
    asm("{ .reg .u64 t; cvta.to.shared.u64 t, %1; cvt.u32.u64 %0, t; }"
        : "=r"(a) : "l"(p));
    return a;
}
__device__ __forceinline__ void cp16(uint32_t dst, const void* src) {
    asm volatile("cp.async.cg.shared.global [%0], [%1], 16;"
                 :: "r"(dst), "l"(src) : "memory");
}
__device__ __forceinline__ void cp_commit() {
    asm volatile("cp.async.commit_group;" ::: "memory");
}
template <int N>
__device__ __forceinline__ void cp_wait() {
    asm volatile("cp.async.wait_group %0;" :: "n"(N) : "memory");
}
__device__ __forceinline__ void ldm_x4(uint32_t (&r)[4], uint32_t addr) {
    asm volatile("ldmatrix.sync.aligned.m8n8.x4.shared.b16 {%0,%1,%2,%3}, [%4];"
                 : "=r"(r[0]), "=r"(r[1]), "=r"(r[2]), "=r"(r[3]) : "r"(addr));
}
__device__ __forceinline__ void mma_f16(float (&d)[4], const uint32_t (&a)[4],
                                        uint32_t b0, uint32_t b1) {
    asm volatile(
        "mma.sync.aligned.m16n8k16.row.col.f32.f16.f16.f32 "
        "{%0,%1,%2,%3}, {%4,%5,%6,%7}, {%8,%9}, {%0,%1,%2,%3};"
        : "+f"(d[0]), "+f"(d[1]), "+f"(d[2]), "+f"(d[3])
        : "r"(a[0]), "r"(a[1]), "r"(a[2]), "r"(a[3]), "r"(b0), "r"(b1));
}

// Dataflow sync
__device__ __forceinline__ void signal_flag(int* flag) {
    __syncthreads();
    if (threadIdx.x == 0) {
        __threadfence();
        atomicAdd(flag, 1);
    }
}
__device__ __forceinline__ void wait_flag(volatile int* flag, int target) {
    if (threadIdx.x == 0) {
        while (*flag < target) { }
        __threadfence();
    }
    __syncthreads();
}

// ---------------------------------------------------------------------------
// Stage loaders. A rows [m0,m0+128) x k[k0,k0+128), B rows [n0,n0+64).
// Split so B (static weights) can be prefetched before flag waits.
// A: 512 thr x 4 cp16;  B: 512 thr x 2 cp16.
// ---------------------------------------------------------------------------
__device__ __forceinline__ void load_stage_A(
    uint32_t sb, const __half* __restrict__ A, int lda, int m0, int k0)
{
    int t = threadIdx.x;
    int r = t >> 2, cb = (t & 3) * 4;
    uint32_t rowoff = (uint32_t)r * ROW_BYTES;
    const __half* pa = A + (size_t)(m0 + r) * lda + k0;
    #pragma unroll
    for (int j = 0; j < 4; j++) {
        int c = cb + j;
        cp16(sb + OFF_A + rowoff + (uint32_t)c * 16, pa + c * 8);
    }
}
__device__ __forceinline__ void load_stage_B(
    uint32_t sb, const __half* __restrict__ B, int ldb, int n0, int k0)
{
    int t = threadIdx.x;
    int r = t >> 3, cb = (t & 7) * 2;
    uint32_t rowoff = (uint32_t)r * ROW_BYTES;
    const __half* pb = B + (size_t)(n0 + r) * ldb + k0;
    cp16(sb + OFF_B + rowoff + (uint32_t)cb * 16, pb + cb * 8);
    cp16(sb + OFF_B + rowoff + (uint32_t)(cb + 1) * 16, pb + (cb + 1) * 8);
}

// ---------------------------------------------------------------------------
// One BK=128 stage. 16 warps in 4(m) x 4(n), warp tile 32x16, acc[2][2][4].
// ---------------------------------------------------------------------------
__device__ __forceinline__ void compute_stage(uint32_t sb, float (&acc)[2][2][4])
{
    int tid = threadIdx.x;
    int lane = tid & 31, wid = tid >> 5;
    int wm = wid >> 2, wn = wid & 3;
    int lr = lane & 15, lc = lane >> 4;
    uint32_t a_base = (uint32_t)(wm * 32 + lr) * ROW_BYTES + (uint32_t)lc * 16;
    uint32_t b_base = (uint32_t)(wn * 16 + lr) * ROW_BYTES + (uint32_t)lc * 16;

    #pragma unroll
    for (int kk = 0; kk < 8; kk++) {
        uint32_t koff = (uint32_t)kk * 32;
        uint32_t a[2][4], b[4];
        #pragma unroll
        for (int mi = 0; mi < 2; mi++)
            ldm_x4(a[mi], sb + OFF_A + a_base + (uint32_t)mi * (16 * ROW_BYTES) + koff);
        ldm_x4(b, sb + OFF_B + b_base + koff);
        #pragma unroll
        for (int mi = 0; mi < 2; mi++) {
            #pragma unroll
            for (int ni = 0; ni < 2; ni++) {
                mma_f16(acc[mi][ni], a[mi], b[ni], b[ni + 2]);
            }
        }
    }
}

// Dual-segment continuous pipeline. If prefetched_b0, stage-0 B load was
// already issued (uncommitted) by the caller.
__device__ void gemm_dual(
    uint32_t sbase,
    const __half* A1, int lda1, const __half* B1, int ldb1, int K1, int kbase1,
    const __half* A2, int lda2, const __half* B2, int ldb2, int K2, int kbase2,
    int m0, int n0, bool prefetched_b0, float (&acc)[2][2][4])
{
    int nst1 = K1 / BK;
    int nst = nst1 + K2 / BK;

    // prologue: stage 0
    if (!prefetched_b0) {
        if (0 < nst1) load_stage_B(sbase, B1, ldb1, n0, kbase1);
        else          load_stage_B(sbase, B2, ldb2, n0, kbase2);
    }
    if (0 < nst1) load_stage_A(sbase, A1, lda1, m0, kbase1);
    else          load_stage_A(sbase, A2, lda2, m0, kbase2);
    cp_commit();

    for (int s = 0; s < nst; s++) {
        cp_wait<0>();
        __syncthreads();
        int nf = s + 1;
        if (nf < nst) {
            uint32_t buf = sbase + (uint32_t)(nf & 1) * STAGE_BYTES;
            if (nf < nst1) {
                load_stage_B(buf, B1, ldb1, n0, kbase1 + nf * BK);
                load_stage_A(buf, A1, lda1, m0, kbase1 + nf * BK);
            } else {
                load_stage_B(buf, B2, ldb2, n0, kbase2 + (nf - nst1) * BK);
                load_stage_A(buf, A2, lda2, m0, kbase2 + (nf - nst1) * BK);
            }
        }
        cp_commit();
        compute_stage(sbase + (uint32_t)(s & 1) * STAGE_BYTES, acc);
    }
}

// ---------------------------------------------------------------------------
// Epilogue: bias / add / rho, write fp16 state and/or fp32. fold_addm:
// write (addm+addm2) back into addm (c2 fold at t=1).
// ---------------------------------------------------------------------------
__device__ void epilogue(
    float (&acc)[2][2][4], int m0, int n0, int outw,
    const float* __restrict__ bias, float* __restrict__ addm,
    const float* __restrict__ addm2, bool fold_addm, bool do_rho,
    __half* __restrict__ oh, float* __restrict__ of)
{
    int tid = threadIdx.x;
    int lane = tid & 31, wid = tid >> 5;
    int wm = wid >> 2, wn = wid & 3;
    int g = lane >> 2, t = lane & 3;

    #pragma unroll
    for (int mi = 0; mi < 2; mi++) {
        #pragma unroll
        for (int ni = 0; ni < 2; ni++) {
            int nc = n0 + wn * 16 + ni * 8 + 2 * t;
            float bv0 = 0.f, bv1 = 0.f;
            if (bias) { bv0 = bias[nc]; bv1 = bias[nc + 1]; }
            #pragma unroll
            for (int h = 0; h < 2; h++) {
                int mr = m0 + wm * 32 + mi * 16 + g + h * 8;
                float v0 = acc[mi][ni][2 * h + 0] + bv0;
                float v1 = acc[mi][ni][2 * h + 1] + bv1;
                size_t o = (size_t)mr * outw + nc;
                if (addm) {
                    float2 av = *(const float2*)&addm[o];
                    float a0 = av.x, a1 = av.y;
                    if (addm2) {
                        float2 av2 = *(const float2*)&addm2[o];
                        a0 += av2.x; a1 += av2.y;
                        if (fold_addm)
                            *(float2*)&addm[o] = make_float2(a0, a1);
                    }
                    v0 += a0; v1 += a1;
                }
                if (do_rho) {
                    v0 = fminf(fmaxf(v0, 0.f), 1.f);
                    v1 = fminf(fmaxf(v1, 0.f), 1.f);
                }
                if (oh) {
                    __half2 hp;
                    hp.x = __float2half_rn(v0);
                    hp.y = __float2half_rn(v1);
                    *(__half2*)&oh[o] = hp;
                }
                if (of) *(float2*)&of[o] = make_float2(v0, v1);
            }
        }
    }
}

// ---------------------------------------------------------------------------
// Persistent kernel, per-m-half pipelines.
// 144 CTAs: [0,16) G0 2x8   [16,80) G1 2x32   [80,144) G2 2x32
// ---------------------------------------------------------------------------
__global__ void __launch_bounds__(THREADS, 1) ep_steps_persist(
    __half* s0base, __half* s1base, __half* s2base,
    const __half* W0, const __half* W1,
    const __half* W0T, const __half* W1T,
    const float* b0, const float* b1,
    float* c2, const float* c2p, float* c1pbase, float* out)
{
    extern __shared__ char dyn[];
    uint32_t sb = smem_u32(dyn);
    const size_t n0e = (size_t)BATCH * D0;
    const size_t n1e = (size_t)BATCH * D1;
    const size_t n2e = (size_t)BATCH * D2;
    int blk = blockIdx.x;
    int group = (blk < 16) ? 0 : (blk < 80 ? 1 : 2);

    // tile coords + m-half
    int m0t, n0t, mh;
    if (group == 0) { m0t = (blk >> 3) * BM; n0t = (blk & 7) * BN; }
    else if (group == 1) { int l = blk - 16; m0t = (l >> 5) * BM; n0t = (l & 31) * BN; }
    else { int l = blk - 80; m0t = (l >> 5) * BM; n0t = (l & 31) * BN; }
    mh = m0t ? 1 : 0;

    for (int t = 1; t <= T_STEPS; t++) {
        int pi = (t - 1) & 1, po = t & 1;
        const __half* i0 = s0base + (size_t)pi * n0e;
        const __half* i1 = s1base + (size_t)pi * n1e;
        const __half* i2 = s2base + (size_t)pi * n2e;
        float* c1p = c1pbase + (size_t)po * n1e;
        bool last = (t == T_STEPS);
        __half *o0 = nullptr, *o1 = nullptr, *o2 = nullptr;
        float *f0 = nullptr, *f1 = nullptr, *f2 = nullptr;
        if (last) {
            f0 = out;
            f1 = out + n0e;
            f2 = out + n0e + n1e;
        } else {
            o0 = s0base + (size_t)po * n0e;
            o1 = s1base + (size_t)po * n1e;
            o2 = s2base + (size_t)po * n2e;
        }

        float acc[2][2][4];
        #pragma unroll
        for (int i = 0; i < 2; i++)
            #pragma unroll
            for (int j = 0; j < 2; j++)
                #pragma unroll
                for (int k = 0; k < 4; k++) acc[i][j][k] = 0.f;

        if (group == 0) {
            // prefetch static weight tile for stage 0, then wait for s1(t-1)
            load_stage_B(sb, W0, D1, n0t, 0);
            if (t > 1) wait_flag(&g_done1[mh], (t - 1) * 32);
            gemm_dual(sb, i1, D1, W0, D1, D1, 0,
                      i1, D1, W0, D1, 0, 0, m0t, n0t, true, acc);
            epilogue(acc, m0t, n0t, D0, b0, nullptr, nullptr, false, true, o0, f0);
            if (t < T_STEPS) signal_flag(&g_done0[mh]);
        } else if (group == 1) {
            load_stage_B(sb, W1, D2, n0t, 0);
            if (t > 1) {
                wait_flag(&g_done2[mh], (t - 1) * 32);   // s2 input
                wait_flag(&g_done0[mh], (t - 1) * 8);    // s0 input
            }
            // 16 stages s2@W1^T + 2 stages s0@W0 (k < 256)
            gemm_dual(sb, i2, D2, W1, D2, D2, 0,
                      i0, D0, W0T, D0, 256, 0, m0t, n0t, true, acc);
            wait_flag(&g_part[mh], t * 32);              // G2 partial ready
            epilogue(acc, m0t, n0t, D1, b1, c1p, nullptr, false, true, o1, f1);
            if (t < T_STEPS) signal_flag(&g_done1[mh]);
        } else {
            load_stage_B(sb, W0T, D0, n0t, 256);
            if (t > 1) {
                wait_flag(&g_done1[mh], (t - 1) * 32);   // s1 input + c1p WAR
                wait_flag(&g_done0[mh], (t - 1) * 8);    // s0 input for partial
            }
            // 2-stage split-K partial: s0[k 256:512] @ W0T
            gemm_dual(sb, i0, D0, W0T, D0, 256, 256,
                      i0, D0, W0T, D0, 0, 0, m0t, n0t, true, acc);
            epilogue(acc, m0t, n0t, D1, nullptr, nullptr, nullptr, false, false,
                     nullptr, c1p);
            signal_flag(&g_part[mh]);
            // own 16-stage s2 update
            #pragma unroll
            for (int i = 0; i < 2; i++)
                #pragma unroll
                for (int j = 0; j < 2; j++)
                    #pragma unroll
                    for (int k = 0; k < 4; k++) acc[i][j][k] = 0.f;
            gemm_dual(sb, i1, D1, W1T, D1, D1, 0,
                      i1, D1, W1T, D1, 0, 0, m0t, n0t, false, acc);
            // t==1: fold c2p into c2 so later steps read one buffer
            epilogue(acc, m0t, n0t, D2, nullptr, c2, (t == 1) ? c2p : nullptr,
                     t == 1, true, o2, f2);
            if (t < T_STEPS) signal_flag(&g_done2[mh]);
        }
    }
}

// C2 split-K: 128 CTAs. half 0: c2 = z(K[0,2048)) + b2. half 1: c2p.
__global__ void __launch_bounds__(THREADS, 1) ep_c2_kernel(
    const __half* dh, const __half* W2, const float* b2,
    float* c2, float* c2p)
{
    extern __shared__ char dyn[];
    uint32_t sb = smem_u32(dyn);

    float acc[2][2][4];
    #pragma unroll
    for (int i = 0; i < 2; i++)
        #pragma unroll
        for (int j = 0; j < 2; j++)
            #pragma unroll
            for (int k = 0; k < 4; k++) acc[i][j][k] = 0.f;

    int blk = blockIdx.x;
    int half = blk >> 6;
    int l = blk & 63;
    int m0 = (l >> 5) * BM, n0 = (l & 31) * BN;
    int kbase = half * (DIN / 2);

    gemm_dual(sb, dh, DIN, W2, DIN, DIN / 2, kbase,
              dh, DIN, W2, DIN, 0, 0, m0, n0, false, acc);

    int tid = threadIdx.x;
    int lane = tid & 31, wid = tid >> 5;
    int wm = wid >> 2, wn = wid & 3;
    int g = lane >> 2, t = lane & 3;
    float* dst = half ? c2p : c2;
    #pragma unroll
    for (int mi = 0; mi < 2; mi++) {
        #pragma unroll
        for (int ni = 0; ni < 2; ni++) {
            int nc = n0 + wn * 16 + ni * 8 + 2 * t;
            float bv0 = half ? 0.f : b2[nc];
            float bv1 = half ? 0.f : b2[nc + 1];
            #pragma unroll
            for (int h = 0; h < 2; h++) {
                int mr = m0 + wm * 32 + mi * 16 + g + h * 8;
                float v0 = acc[mi][ni][2 * h + 0] + bv0;
                float v1 = acc[mi][ni][2 * h + 1] + bv1;
                *(float2*)&dst[(size_t)mr * D2 + nc] = make_float2(v0, v1);
            }
        }
    }
}

// ====================== fused conversion kernel ============================
__device__ __forceinline__ void vec4_to_h(const float* x, __half* h, int idx) {
    float4 v = *(const float4*)&x[idx];
    __half2 p0, p1;
    p0.x = __float2half_rn(v.x); p0.y = __float2half_rn(v.y);
    p1.x = __float2half_rn(v.z); p1.y = __float2half_rn(v.w);
    *(__half2*)&h[idx] = p0;
    *(__half2*)&h[idx + 2] = p1;
}

// block ranges (each non-transpose block converts 1024 elems)
#define CB_W1   1024
#define CB_W2   5120
#define CB_DATA 13312
#define CB_S0   14336
#define CB_S1   14464
#define CB_S2   14976
#define CB_W0T  15488
#define CB_W1T  16512
#define CB_TOTAL 20608

__global__ void __launch_bounds__(256) fused_convert(
    const float* __restrict__ W0, const float* __restrict__ W1,
    const float* __restrict__ W2, const float* __restrict__ data,
    const float* __restrict__ s0, const float* __restrict__ s1,
    const float* __restrict__ s2,
    __half* hW0, __half* hW1, __half* hW0T, __half* hW1T,
    __half* hW2, __half* hd,
    __half* hs0, __half* hs1, __half* hs2)
{
    __shared__ float tile[32][33];
    int b = blockIdx.x, tid = threadIdx.x;
    if (b == 0 && tid < 2) {
        g_done0[tid] = 0; g_done1[tid] = 0; g_done2[tid] = 0; g_part[tid] = 0;
    }

    if (b < CB_W1) {
        vec4_to_h(W0, hW0, (b * 256 + tid) * 4);
    } else if (b < CB_W2) {
        vec4_to_h(W1, hW1, ((b - CB_W1) * 256 + tid) * 4);
    } else if (b < CB_DATA) {
        vec4_to_h(W2, hW2, ((b - CB_W2) * 256 + tid) * 4);
    } else if (b < CB_S0) {
        vec4_to_h(data, hd, ((b - CB_DATA) * 256 + tid) * 4);
    } else if (b < CB_S1) {
        vec4_to_h(s0, hs0, ((b - CB_S0) * 256 + tid) * 4);
    } else if (b < CB_S2) {
        vec4_to_h(s1, hs1, ((b - CB_S1) * 256 + tid) * 4);
    } else if (b < CB_W0T) {
        vec4_to_h(s2, hs2, ((b - CB_S2) * 256 + tid) * 4);
    } else if (b < CB_W1T) {
        int local = b - CB_W0T;
        int bx = local % (D1 / 32), by = local / (D1 / 32);
        int tx = tid & 31, ty = tid >> 5;
        int c0 = bx * 32, r0 = by * 32;
        #pragma unroll
        for (int k = 0; k < 4; k++)
            tile[ty + 8 * k][tx] = W0[(size_t)(r0 + ty + 8 * k) * D1 + c0 + tx];
        __syncthreads();
        #pragma unroll
        for (int k = 0; k < 4; k++) {
            size_t o = (size_t)(c0 + ty + 8 * k) * D0 + r0 + tx;
            hW0T[o] = __float2half_rn(tile[tx][ty + 8 * k]);
        }
    } else {
        int local = b - CB_W1T;
        int bx = local % (D2 / 32), by = local / (D2 / 32);
        int tx = tid & 31, ty = tid >> 5;
        int c0 = bx * 32, r0 = by * 32;
        #pragma unroll
        for (int k = 0; k < 4; k++)
            tile[ty + 8 * k][tx] = W1[(size_t)(r0 + ty + 8 * k) * D2 + c0 + tx];
        __syncthreads();
        #pragma unroll
        for (int k = 0; k < 4; k++) {
            size_t o = (size_t)(c0 + ty + 8 * k) * D1 + r0 + tx;
            hW1T[o] = __float2half_rn(tile[tx][ty + 8 * k]);
        }
    }
}

// ------------------------------- host side ---------------------------------
static inline void* sym(const void* s) {
    void* p = nullptr;
    cudaGetSymbolAddress(&p, s);
    return p;
}

extern "C" void kernel_launch(void* const* d_in, const int* in_sizes, int n_in,
                              void* d_out, int out_size)
{
    const float* data = (const float*)d_in[0];
    const float* in_s0 = (const float*)d_in[1];
    const float* in_s1 = (const float*)d_in[2];
    const float* in_s2 = (const float*)d_in[3];
    const float* W0 = (const float*)d_in[4];
    const float* b0 = (const float*)d_in[5];
    const float* W1 = (const float*)d_in[6];
    const float* b1 = (const float*)d_in[7];
    const float* W2 = (const float*)d_in[8];
    const float* b2 = (const float*)d_in[9];
    float* out = (float*)d_out;

    cudaFuncSetAttribute(ep_steps_persist, cudaFuncAttributeMaxDynamicSharedMemorySize, DSMEM_BYTES);
    cudaFuncSetAttribute(ep_c2_kernel,     cudaFuncAttributeMaxDynamicSharedMemorySize, DSMEM_BYTES);

    __half *hW0 = (__half*)sym(g_hW0), *hW1 = (__half*)sym(g_hW1);
    __half *hW0T = (__half*)sym(g_hW0T), *hW1T = (__half*)sym(g_hW1T);
    __half *hW2 = (__half*)sym(g_hW2), *hd = (__half*)sym(g_hd);
    __half *hs0 = (__half*)sym(g_hs0);
    __half *hs1 = (__half*)sym(g_hs1);
    __half *hs2 = (__half*)sym(g_hs2);
    float* c2 = (float*)sym(g_c2);
    float* c2p = (float*)sym(g_c2p);
    float* c1p = (float*)sym(g_c1p);

    fused_convert<<<CB_TOTAL, 256>>>(
        W0, W1, W2, data, in_s0, in_s1, in_s2,
        hW0, hW1, hW0T, hW1T, hW2, hd, hs0, hs1, hs2);

    ep_c2_kernel<<<128, THREADS, DSMEM_BYTES>>>(hd, hW2, b2, c2, c2p);

    ep_steps_persist<<<144, THREADS, DSMEM_BYTES>>>(
        hs0, hs1, hs2,
        hW0, hW1, hW0T, hW1T,
        b0, b1, c2, c2p, c1p, out);
}

// round 12
// speedup vs baseline: 1.1550x; 1.1550x over previous
#include <cuda_runtime.h>
#include <cuda_fp16.h>
#include <cstdint>
#include <cstddef>

// ---------------------------------------------------------------------------
// EP free-phase relaxation. Persistent single-pass fp16 mma.sync kernel,
// 512 threads/CTA (16 warps 4x4), BK=64 DEPTH=4 pipeline (proven R10 core),
// per-m-half dataflow flags, stage-0 weight prefetch before flag waits,
// split-K rebalance (G2 computes 4 stages of G1's s0@W0 term), c2 fold at t=1.
//   G0 (16 CTAs): s0' = rho(s1 W0^T + b0)                      32 stages
//   G1 (64 CTAs): s1' = rho(s2 W1^T + s0 W0[k<256] + c1p + b1) 36 stages
//   G2 (64 CTAs): c1p = s0 W0[k 256:512] (4 st) then s2' (32)  36 stages
// C2 = data@W2^T + b2 split-K over 128 CTAs (c2 + c2p, folded at t=1).
// ---------------------------------------------------------------------------

#define BATCH 256
#define D0 512
#define D1 2048
#define D2 2048
#define DIN 4096
#define T_STEPS 20

#define BM 128
#define BN 64
#define BK 64
#define DEPTH 4
#define THREADS 512

#define ROW_BYTES 144                    // 64 halves (128B) + 16B pad
#define A_MAT (128 * ROW_BYTES)          // 18432
#define B_MAT (64 * ROW_BYTES)           // 9216
#define OFF_A 0
#define OFF_B (A_MAT)
#define STAGE_BYTES (A_MAT + B_MAT)      // 27648
#define DSMEM_BYTES (DEPTH * STAGE_BYTES) // 110592

// --------------------------- device scratch --------------------------------
__device__ __half g_hW0[D0 * D1];
__device__ __half g_hW1[D1 * D2];
__device__ __half g_hW0T[D1 * D0];
__device__ __half g_hW1T[D2 * D1];
__device__ __half g_hW2[D2 * DIN];
__device__ __half g_hd[BATCH * DIN];
__device__ __half g_hs0[2][BATCH * D0];
__device__ __half g_hs1[2][BATCH * D1];
__device__ __half g_hs2[2][BATCH * D2];
__device__ float g_c2[BATCH * D2];
__device__ float g_c2p[BATCH * D2];
__device__ float g_c1p[2][BATCH * D1];        // split-K partial (parity)
__device__ int g_done0[2], g_done1[2], g_done2[2];  // per-m-half counters
__device__ int g_part[2];                     // per-m-half partial counters

// ------------------------------ PTX helpers --------------------------------
__device__ __forceinline__ uint32_t smem_u32(const void* p) {
    uint32_t a;
    asm("{ .reg .u64 t; cvta.to.shared.u64 t, %1; cvt.u32.u64 %0, t; }"
        : "=r"(a) : "l"(p));
    return a;
}
__device__ __forceinline__ void cp16(uint32_t dst, const void* src) {
    asm volatile("cp.async.cg.shared.global [%0], [%1], 16;"
                 :: "r"(dst), "l"(src) : "memory");
}
__device__ __forceinline__ void cp_commit() {
    asm volatile("cp.async.commit_group;" ::: "memory");
}
template <int N>
__device__ __forceinline__ void cp_wait() {
    asm volatile("cp.async.wait_group %0;" :: "n"(N) : "memory");
}
__device__ __forceinline__ void ldm_x4(uint32_t (&r)[4], uint32_t addr) {
    asm volatile("ldmatrix.sync.aligned.m8n8.x4.shared.b16 {%0,%1,%2,%3}, [%4];"
                 : "=r"(r[0]), "=r"(r[1]), "=r"(r[2]), "=r"(r[3]) : "r"(addr));
}
__device__ __forceinline__ void mma_f16(float (&d)[4], const uint32_t (&a)[4],
                                        uint32_t b0, uint32_t b1) {
    asm volatile(
        "mma.sync.aligned.m16n8k16.row.col.f32.f16.f16.f32 "
        "{%0,%1,%2,%3}, {%4,%5,%6,%7}, {%8,%9}, {%0,%1,%2,%3};"
        : "+f"(d[0]), "+f"(d[1]), "+f"(d[2]), "+f"(d[3])
        : "r"(a[0]), "r"(a[1]), "r"(a[2]), "r"(a[3]), "r"(b0), "r"(b1));
}

// Dataflow sync
__device__ __forceinline__ void signal_flag(int* flag) {
    __syncthreads();
    if (threadIdx.x == 0) {
        __threadfence();
        atomicAdd(flag, 1);
    }
}
__device__ __forceinline__ void wait_flag(volatile int* flag, int target) {
    if (threadIdx.x == 0) {
        while (*flag < target) { }
        __threadfence();
    }
    __syncthreads();
}

// ---------------------------------------------------------------------------
// Stage loaders (split so static-weight B can be prefetched before waits).
// A rows [m0,m0+128) x k[k0,k0+64): 512 thr x 2 cp16.
// B rows [n0,n0+64): 512 thr x 1 cp16.
// ---------------------------------------------------------------------------
__device__ __forceinline__ void load_stage_A(
    uint32_t sb, const __half* __restrict__ A, int lda, int m0, int k0)
{
    int t = threadIdx.x;
    int r = t >> 2, cb = (t & 3) * 2;
    uint32_t rowoff = (uint32_t)r * ROW_BYTES;
    const __half* pa = A + (size_t)(m0 + r) * lda + k0;
    cp16(sb + OFF_A + rowoff + (uint32_t)cb * 16, pa + cb * 8);
    cp16(sb + OFF_A + rowoff + (uint32_t)(cb + 1) * 16, pa + (cb + 1) * 8);
}
__device__ __forceinline__ void load_stage_B(
    uint32_t sb, const __half* __restrict__ B, int ldb, int n0, int k0)
{
    int t = threadIdx.x;
    int r = t >> 3, c = t & 7;
    const __half* pb = B + (size_t)(n0 + r) * ldb + k0;
    cp16(sb + OFF_B + (uint32_t)r * ROW_BYTES + (uint32_t)c * 16, pb + c * 8);
}

// ---------------------------------------------------------------------------
// One BK=64 stage. 16 warps in 4(m) x 4(n), warp tile 32x16, acc[2][2][4].
// ---------------------------------------------------------------------------
__device__ __forceinline__ void compute_stage(uint32_t sb, float (&acc)[2][2][4])
{
    int tid = threadIdx.x;
    int lane = tid & 31, wid = tid >> 5;
    int wm = wid >> 2, wn = wid & 3;
    int lr = lane & 15, lc = lane >> 4;
    uint32_t a_base = (uint32_t)(wm * 32 + lr) * ROW_BYTES + (uint32_t)lc * 16;
    uint32_t b_base = (uint32_t)(wn * 16 + lr) * ROW_BYTES + (uint32_t)lc * 16;

    #pragma unroll
    for (int kk = 0; kk < 4; kk++) {
        uint32_t koff = (uint32_t)kk * 32;
        uint32_t a[2][4], b[4];
        #pragma unroll
        for (int mi = 0; mi < 2; mi++)
            ldm_x4(a[mi], sb + OFF_A + a_base + (uint32_t)mi * (16 * ROW_BYTES) + koff);
        ldm_x4(b, sb + OFF_B + b_base + koff);
        #pragma unroll
        for (int mi = 0; mi < 2; mi++) {
            #pragma unroll
            for (int ni = 0; ni < 2; ni++) {
                mma_f16(acc[mi][ni], a[mi], b[ni], b[ni + 2]);
            }
        }
    }
}

// Dual-segment continuous pipeline, DEPTH=4, wait<2> (2 stages in flight).
// If prefetched_b0, stage-0 B load was already issued (uncommitted) by caller.
__device__ void gemm_dual(
    uint32_t sbase,
    const __half* A1, int lda1, const __half* B1, int ldb1, int K1, int kbase1,
    const __half* A2, int lda2, const __half* B2, int ldb2, int K2, int kbase2,
    int m0, int n0, bool prefetched_b0, float (&acc)[2][2][4])
{
    int nst1 = K1 / BK;
    int nst = nst1 + K2 / BK;

    #pragma unroll
    for (int p = 0; p < DEPTH - 1; p++) {
        if (p < nst) {
            uint32_t buf = sbase + (uint32_t)p * STAGE_BYTES;
            if (p < nst1) {
                if (p != 0 || !prefetched_b0)
                    load_stage_B(buf, B1, ldb1, n0, kbase1 + p * BK);
                load_stage_A(buf, A1, lda1, m0, kbase1 + p * BK);
            } else {
                if (p != 0 || !prefetched_b0)
                    load_stage_B(buf, B2, ldb2, n0, kbase2 + (p - nst1) * BK);
                load_stage_A(buf, A2, lda2, m0, kbase2 + (p - nst1) * BK);
            }
        }
        cp_commit();
    }
    for (int s = 0; s < nst; s++) {
        cp_wait<DEPTH - 2>();
        __syncthreads();
        int nf = s + DEPTH - 1;
        if (nf < nst) {
            uint32_t buf = sbase + (uint32_t)(nf % DEPTH) * STAGE_BYTES;
            if (nf < nst1) {
                load_stage_B(buf, B1, ldb1, n0, kbase1 + nf * BK);
                load_stage_A(buf, A1, lda1, m0, kbase1 + nf * BK);
            } else {
                load_stage_B(buf, B2, ldb2, n0, kbase2 + (nf - nst1) * BK);
                load_stage_A(buf, A2, lda2, m0, kbase2 + (nf - nst1) * BK);
            }
        }
        cp_commit();
        compute_stage(sbase + (uint32_t)(s % DEPTH) * STAGE_BYTES, acc);
    }
}

// ---------------------------------------------------------------------------
// Epilogue: bias / add / rho, write fp16 state and/or fp32. fold_addm:
// write (addm+addm2) back into addm (c2 fold at t=1).
// ---------------------------------------------------------------------------
__device__ void epilogue(
    float (&acc)[2][2][4], int m0, int n0, int outw,
    const float* __restrict__ bias, float* __restrict__ addm,
    const float* __restrict__ addm2, bool fold_addm, bool do_rho,
    __half* __restrict__ oh, float* __restrict__ of)
{
    int tid = threadIdx.x;
    int lane = tid & 31, wid = tid >> 5;
    int wm = wid >> 2, wn = wid & 3;
    int g = lane >> 2, t = lane & 3;

    #pragma unroll
    for (int mi = 0; mi < 2; mi++) {
        #pragma unroll
        for (int ni = 0; ni < 2; ni++) {
            int nc = n0 + wn * 16 + ni * 8 + 2 * t;
            float bv0 = 0.f, bv1 = 0.f;
            if (bias) { bv0 = bias[nc]; bv1 = bias[nc + 1]; }
            #pragma unroll
            for (int h = 0; h < 2; h++) {
                int mr = m0 + wm * 32 + mi * 16 + g + h * 8;
                float v0 = acc[mi][ni][2 * h + 0] + bv0;
                float v1 = acc[mi][ni][2 * h + 1] + bv1;
                size_t o = (size_t)mr * outw + nc;
                if (addm) {
                    float2 av = *(const float2*)&addm[o];
                    float a0 = av.x, a1 = av.y;
                    if (addm2) {
                        float2 av2 = *(const float2*)&addm2[o];
                        a0 += av2.x; a1 += av2.y;
                        if (fold_addm)
                            *(float2*)&addm[o] = make_float2(a0, a1);
                    }
                    v0 += a0; v1 += a1;
                }
                if (do_rho) {
                    v0 = fminf(fmaxf(v0, 0.f), 1.f);
                    v1 = fminf(fmaxf(v1, 0.f), 1.f);
                }
                if (oh) {
                    __half2 hp;
                    hp.x = __float2half_rn(v0);
                    hp.y = __float2half_rn(v1);
                    *(__half2*)&oh[o] = hp;
                }
                if (of) *(float2*)&of[o] = make_float2(v0, v1);
            }
        }
    }
}

// ---------------------------------------------------------------------------
// Persistent kernel, per-m-half pipelines.
// 144 CTAs: [0,16) G0 2x8   [16,80) G1 2x32   [80,144) G2 2x32
// ---------------------------------------------------------------------------
__global__ void __launch_bounds__(THREADS, 1) ep_steps_persist(
    __half* s0base, __half* s1base, __half* s2base,
    const __half* W0, const __half* W1,
    const __half* W0T, const __half* W1T,
    const float* b0, const float* b1,
    float* c2, const float* c2p, float* c1pbase, float* out)
{
    extern __shared__ char dyn[];
    uint32_t sb = smem_u32(dyn);
    const size_t n0e = (size_t)BATCH * D0;
    const size_t n1e = (size_t)BATCH * D1;
    const size_t n2e = (size_t)BATCH * D2;
    int blk = blockIdx.x;
    int group = (blk < 16) ? 0 : (blk < 80 ? 1 : 2);

    int m0t, n0t;
    if (group == 0) { m0t = (blk >> 3) * BM; n0t = (blk & 7) * BN; }
    else if (group == 1) { int l = blk - 16; m0t = (l >> 5) * BM; n0t = (l & 31) * BN; }
    else { int l = blk - 80; m0t = (l >> 5) * BM; n0t = (l & 31) * BN; }
    int mh = m0t ? 1 : 0;

    for (int t = 1; t <= T_STEPS; t++) {
        int pi = (t - 1) & 1, po = t & 1;
        const __half* i0 = s0base + (size_t)pi * n0e;
        const __half* i1 = s1base + (size_t)pi * n1e;
        const __half* i2 = s2base + (size_t)pi * n2e;
        float* c1p = c1pbase + (size_t)po * n1e;
        bool last = (t == T_STEPS);
        __half *o0 = nullptr, *o1 = nullptr, *o2 = nullptr;
        float *f0 = nullptr, *f1 = nullptr, *f2 = nullptr;
        if (last) {
            f0 = out;
            f1 = out + n0e;
            f2 = out + n0e + n1e;
        } else {
            o0 = s0base + (size_t)po * n0e;
            o1 = s1base + (size_t)po * n1e;
            o2 = s2base + (size_t)po * n2e;
        }

        float acc[2][2][4];
        #pragma unroll
        for (int i = 0; i < 2; i++)
            #pragma unroll
            for (int j = 0; j < 2; j++)
                #pragma unroll
                for (int k = 0; k < 4; k++) acc[i][j][k] = 0.f;

        if (group == 0) {
            // prefetch stage-0 weight tile, then wait for s1(t-1) of own half
            load_stage_B(sb, W0, D1, n0t, 0);
            if (t > 1) wait_flag(&g_done1[mh], (t - 1) * 32);
            gemm_dual(sb, i1, D1, W0, D1, D1, 0,
                      i1, D1, W0, D1, 0, 0, m0t, n0t, true, acc);
            epilogue(acc, m0t, n0t, D0, b0, nullptr, nullptr, false, true, o0, f0);
            if (t < T_STEPS) signal_flag(&g_done0[mh]);
        } else if (group == 1) {
            load_stage_B(sb, W1, D2, n0t, 0);
            if (t > 1) {
                wait_flag(&g_done2[mh], (t - 1) * 32);   // s2 input
                wait_flag(&g_done0[mh], (t - 1) * 8);    // s0 input
            }
            // 32 stages s2@W1^T + 4 stages s0@W0 (k < 256)
            gemm_dual(sb, i2, D2, W1, D2, D2, 0,
                      i0, D0, W0T, D0, 256, 0, m0t, n0t, true, acc);
            wait_flag(&g_part[mh], t * 32);              // G2 partial ready
            epilogue(acc, m0t, n0t, D1, b1, c1p, nullptr, false, true, o1, f1);
            if (t < T_STEPS) signal_flag(&g_done1[mh]);
        } else {
            load_stage_B(sb, W0T, D0, n0t, 256);
            if (t > 1) {
                wait_flag(&g_done1[mh], (t - 1) * 32);   // s1 input + c1p WAR
                wait_flag(&g_done0[mh], (t - 1) * 8);    // s0 input for partial
            }
            // 4-stage split-K partial: s0[k 256:512] @ W0T
            gemm_dual(sb, i0, D0, W0T, D0, 256, 256,
                      i0, D0, W0T, D0, 0, 0, m0t, n0t, true, acc);
            epilogue(acc, m0t, n0t, D1, nullptr, nullptr, nullptr, false, false,
                     nullptr, c1p);
            signal_flag(&g_part[mh]);
            // own 32-stage s2 update
            #pragma unroll
            for (int i = 0; i < 2; i++)
                #pragma unroll
                for (int j = 0; j < 2; j++)
                    #pragma unroll
                    for (int k = 0; k < 4; k++) acc[i][j][k] = 0.f;
            gemm_dual(sb, i1, D1, W1T, D1, D1, 0,
                      i1, D1, W1T, D1, 0, 0, m0t, n0t, false, acc);
            // t==1: fold c2p into c2 so later steps read one buffer
            epilogue(acc, m0t, n0t, D2, nullptr, c2, (t == 1) ? c2p : nullptr,
                     t == 1, true, o2, f2);
            if (t < T_STEPS) signal_flag(&g_done2[mh]);
        }
    }
}

// C2 split-K: 128 CTAs. half 0: c2 = z(K[0,2048)) + b2. half 1: c2p.
__global__ void __launch_bounds__(THREADS, 1) ep_c2_kernel(
    const __half* dh, const __half* W2, const float* b2,
    float* c2, float* c2p)
{
    extern __shared__ char dyn[];
    uint32_t sb = smem_u32(dyn);

    float acc[2][2][4];
    #pragma unroll
    for (int i = 0; i < 2; i++)
        #pragma unroll
        for (int j = 0; j < 2; j++)
            #pragma unroll
            for (int k = 0; k < 4; k++) acc[i][j][k] = 0.f;

    int blk = blockIdx.x;
    int half = blk >> 6;
    int l = blk & 63;
    int m0 = (l >> 5) * BM, n0 = (l & 31) * BN;
    int kbase = half * (DIN / 2);

    gemm_dual(sb, dh, DIN, W2, DIN, DIN / 2, kbase,
              dh, DIN, W2, DIN, 0, 0, m0, n0, false, acc);

    int tid = threadIdx.x;
    int lane = tid & 31, wid = tid >> 5;
    int wm = wid >> 2, wn = wid & 3;
    int g = lane >> 2, t = lane & 3;
    float* dst = half ? c2p : c2;
    #pragma unroll
    for (int mi = 0; mi < 2; mi++) {
        #pragma unroll
        for (int ni = 0; ni < 2; ni++) {
            int nc = n0 + wn * 16 + ni * 8 + 2 * t;
            float bv0 = half ? 0.f : b2[nc];
            float bv1 = half ? 0.f : b2[nc + 1];
            #pragma unroll
            for (int h = 0; h < 2; h++) {
                int mr = m0 + wm * 32 + mi * 16 + g + h * 8;
                float v0 = acc[mi][ni][2 * h + 0] + bv0;
                float v1 = acc[mi][ni][2 * h + 1] + bv1;
                *(float2*)&dst[(size_t)mr * D2 + nc] = make_float2(v0, v1);
            }
        }
    }
}

// ====================== fused conversion kernel ============================
__device__ __forceinline__ void vec4_to_h(const float* x, __half* h, int idx) {
    float4 v = *(const float4*)&x[idx];
    __half2 p0, p1;
    p0.x = __float2half_rn(v.x); p0.y = __float2half_rn(v.y);
    p1.x = __float2half_rn(v.z); p1.y = __float2half_rn(v.w);
    *(__half2*)&h[idx] = p0;
    *(__half2*)&h[idx + 2] = p1;
}

// block ranges (each non-transpose block converts 1024 elems)
#define CB_W1   1024
#define CB_W2   5120
#define CB_DATA 13312
#define CB_S0   14336
#define CB_S1   14464
#define CB_S2   14976
#define CB_W0T  15488
#define CB_W1T  16512
#define CB_TOTAL 20608

__global__ void __launch_bounds__(256) fused_convert(
    const float* __restrict__ W0, const float* __restrict__ W1,
    const float* __restrict__ W2, const float* __restrict__ data,
    const float* __restrict__ s0, const float* __restrict__ s1,
    const float* __restrict__ s2,
    __half* hW0, __half* hW1, __half* hW0T, __half* hW1T,
    __half* hW2, __half* hd,
    __half* hs0, __half* hs1, __half* hs2)
{
    __shared__ float tile[32][33];
    int b = blockIdx.x, tid = threadIdx.x;
    if (b == 0 && tid < 2) {
        g_done0[tid] = 0; g_done1[tid] = 0; g_done2[tid] = 0; g_part[tid] = 0;
    }

    if (b < CB_W1) {
        vec4_to_h(W0, hW0, (b * 256 + tid) * 4);
    } else if (b < CB_W2) {
        vec4_to_h(W1, hW1, ((b - CB_W1) * 256 + tid) * 4);
    } else if (b < CB_DATA) {
        vec4_to_h(W2, hW2, ((b - CB_W2) * 256 + tid) * 4);
    } else if (b < CB_S0) {
        vec4_to_h(data, hd, ((b - CB_DATA) * 256 + tid) * 4);
    } else if (b < CB_S1) {
        vec4_to_h(s0, hs0, ((b - CB_S0) * 256 + tid) * 4);
    } else if (b < CB_S2) {
        vec4_to_h(s1, hs1, ((b - CB_S1) * 256 + tid) * 4);
    } else if (b < CB_W0T) {
        vec4_to_h(s2, hs2, ((b - CB_S2) * 256 + tid) * 4);
    } else if (b < CB_W1T) {
        int local = b - CB_W0T;
        int bx = local % (D1 / 32), by = local / (D1 / 32);
        int tx = tid & 31, ty = tid >> 5;
        int c0 = bx * 32, r0 = by * 32;
        #pragma unroll
        for (int k = 0; k < 4; k++)
            tile[ty + 8 * k][tx] = W0[(size_t)(r0 + ty + 8 * k) * D1 + c0 + tx];
        __syncthreads();
        #pragma unroll
        for (int k = 0; k < 4; k++) {
            size_t o = (size_t)(c0 + ty + 8 * k) * D0 + r0 + tx;
            hW0T[o] = __float2half_rn(tile[tx][ty + 8 * k]);
        }
    } else {
        int local = b - CB_W1T;
        int bx = local % (D2 / 32), by = local / (D2 / 32);
        int tx = tid & 31, ty = tid >> 5;
        int c0 = bx * 32, r0 = by * 32;
        #pragma unroll
        for (int k = 0; k < 4; k++)
            tile[ty + 8 * k][tx] = W1[(size_t)(r0 + ty + 8 * k) * D2 + c0 + tx];
        __syncthreads();
        #pragma unroll
        for (int k = 0; k < 4; k++) {
            size_t o = (size_t)(c0 + ty + 8 * k) * D1 + r0 + tx;
            hW1T[o] = __float2half_rn(tile[tx][ty + 8 * k]);
        }
    }
}

// ------------------------------- host side ---------------------------------
static inline void* sym(const void* s) {
    void* p = nullptr;
    cudaGetSymbolAddress(&p, s);
    return p;
}

extern "C" void kernel_launch(void* const* d_in, const int* in_sizes, int n_in,
                              void* d_out, int out_size)
{
    const float* data = (const float*)d_in[0];
    const float* in_s0 = (const float*)d_in[1];
    const float* in_s1 = (const float*)d_in[2];
    const float* in_s2 = (const float*)d_in[3];
    const float* W0 = (const float*)d_in[4];
    const float* b0 = (const float*)d_in[5];
    const float* W1 = (const float*)d_in[6];
    const float* b1 = (const float*)d_in[7];
    const float* W2 = (const float*)d_in[8];
    const float* b2 = (const float*)d_in[9];
    float* out = (float*)d_out;

    cudaFuncSetAttribute(ep_steps_persist, cudaFuncAttributeMaxDynamicSharedMemorySize, DSMEM_BYTES);
    cudaFuncSetAttribute(ep_c2_kernel,     cudaFuncAttributeMaxDynamicSharedMemorySize, DSMEM_BYTES);

    __half *hW0 = (__half*)sym(g_hW0), *hW1 = (__half*)sym(g_hW1);
    __half *hW0T = (__half*)sym(g_hW0T), *hW1T = (__half*)sym(g_hW1T);
    __half *hW2 = (__half*)sym(g_hW2), *hd = (__half*)sym(g_hd);
    __half *hs0 = (__half*)sym(g_hs0);
    __half *hs1 = (__half*)sym(g_hs1);
    __half *hs2 = (__half*)sym(g_hs2);
    float* c2 = (float*)sym(g_c2);
    float* c2p = (float*)sym(g_c2p);
    float* c1p = (float*)sym(g_c1p);

    fused_convert<<<CB_TOTAL, 256>>>(
        W0, W1, W2, data, in_s0, in_s1, in_s2,
        hW0, hW1, hW0T, hW1T, hW2, hd, hs0, hs1, hs2);

    ep_c2_kernel<<<128, THREADS, DSMEM_BYTES>>>(hd, hW2, b2, c2, c2p);

    ep_steps_persist<<<144, THREADS, DSMEM_BYTES>>>(
        hs0, hs1, hs2,
        hW0, hW1, hW0T, hW1T,
        b0, b1, c2, c2p, c1p, out);
}

// round 14
// speedup vs baseline: 1.1802x; 1.0218x over previous
#include <cuda_runtime.h>
#include <cuda_fp16.h>
#include <cstdint>
#include <cstddef>

// ---------------------------------------------------------------------------
// EP free-phase relaxation. Persistent single-pass fp16 mma.sync kernel,
// 512 threads/CTA (16 warps 4x4). Pipeline: 2-stage groups, 3-group (6-stage)
// circular smem buffer, cp_wait<1> in group units -> 18 barriers/step with
// 4-stage lookahead. Per-m-half dataflow flags, stage-0 weight prefetch,
// split-K rebalance (G2 does 4 stages of G1's s0@W0), c2 fold at t=1.
//   G0 (16 CTAs): s0' = rho(s1 W0^T + b0)                      32 stages
//   G1 (64 CTAs): s1' = rho(s2 W1^T + s0 W0[k<256] + c1p + b1) 36 stages
//   G2 (64 CTAs): c1p = s0 W0[k 256:512] (4 st) then s2' (32)  36 stages
// C2 = data@W2^T + b2 split-K over 128 CTAs (c2 + c2p, folded at t=1).
// ---------------------------------------------------------------------------

#define BATCH 256
#define D0 512
#define D1 2048
#define D2 2048
#define DIN 4096
#define T_STEPS 20

#define BM 128
#define BN 64
#define BK 64
#define THREADS 512

#define ROW_BYTES 144                    // 64 halves (128B) + 16B pad
#define A_MAT (128 * ROW_BYTES)          // 18432
#define B_MAT (64 * ROW_BYTES)           // 9216
#define OFF_A 0
#define OFF_B (A_MAT)
#define STAGE_BYTES (A_MAT + B_MAT)      // 27648
#define DEPTH_G 3                        // groups in flight
#define GROUP_BYTES (2 * STAGE_BYTES)    // 55296
#define DSMEM_BYTES (DEPTH_G * GROUP_BYTES) // 165888

// --------------------------- device scratch --------------------------------
__device__ __half g_hW0[D0 * D1];
__device__ __half g_hW1[D1 * D2];
__device__ __half g_hW0T[D1 * D0];
__device__ __half g_hW1T[D2 * D1];
__device__ __half g_hW2[D2 * DIN];
__device__ __half g_hd[BATCH * DIN];
__device__ __half g_hs0[2][BATCH * D0];
__device__ __half g_hs1[2][BATCH * D1];
__device__ __half g_hs2[2][BATCH * D2];
__device__ float g_c2[BATCH * D2];
__device__ float g_c2p[BATCH * D2];
__device__ float g_c1p[2][BATCH * D1];        // split-K partial (parity)
__device__ int g_done0[2], g_done1[2], g_done2[2];  // per-m-half counters
__device__ int g_part[2];                     // per-m-half partial counters

// ------------------------------ PTX helpers --------------------------------
__device__ __forceinline__ uint32_t smem_u32(const void* p) {
    uint32_t a;
    asm("{ .reg .u64 t; cvta.to.shared.u64 t, %1; cvt.u32.u64 %0, t; }"
        : "=r"(a) : "l"(p));
    return a;
}
__device__ __forceinline__ void cp16(uint32_t dst, const void* src) {
    asm volatile("cp.async.cg.shared.global [%0], [%1], 16;"
                 :: "r"(dst), "l"(src) : "memory");
}
__device__ __forceinline__ void cp_commit() {
    asm volatile("cp.async.commit_group;" ::: "memory");
}
template <int N>
__device__ __forceinline__ void cp_wait() {
    asm volatile("cp.async.wait_group %0;" :: "n"(N) : "memory");
}
__device__ __forceinline__ void ldm_x4(uint32_t (&r)[4], uint32_t addr) {
    asm volatile("ldmatrix.sync.aligned.m8n8.x4.shared.b16 {%0,%1,%2,%3}, [%4];"
                 : "=r"(r[0]), "=r"(r[1]), "=r"(r[2]), "=r"(r[3]) : "r"(addr));
}
__device__ __forceinline__ void mma_f16(float (&d)[4], const uint32_t (&a)[4],
                                        uint32_t b0, uint32_t b1) {
    asm volatile(
        "mma.sync.aligned.m16n8k16.row.col.f32.f16.f16.f32 "
        "{%0,%1,%2,%3}, {%4,%5,%6,%7}, {%8,%9}, {%0,%1,%2,%3};"
        : "+f"(d[0]), "+f"(d[1]), "+f"(d[2]), "+f"(d[3])
        : "r"(a[0]), "r"(a[1]), "r"(a[2]), "r"(a[3]), "r"(b0), "r"(b1));
}

// Dataflow sync
__device__ __forceinline__ void signal_flag(int* flag) {
    __syncthreads();
    if (threadIdx.x == 0) {
        __threadfence();
        atomicAdd(flag, 1);
    }
}
__device__ __forceinline__ void wait_flag(volatile int* flag, int target) {
    if (threadIdx.x == 0) {
        while (*flag < target) { }
        __threadfence();
    }
    __syncthreads();
}

// ---------------------------------------------------------------------------
// Stage loaders. A rows [m0,m0+128) x k[k0,k0+64): 512 thr x 2 cp16.
// B rows [n0,n0+64): 512 thr x 1 cp16.
// ---------------------------------------------------------------------------
__device__ __forceinline__ void load_stage_A(
    uint32_t sb, const __half* __restrict__ A, int lda, int m0, int k0)
{
    int t = threadIdx.x;
    int r = t >> 2, cb = (t & 3) * 2;
    uint32_t rowoff = (uint32_t)r * ROW_BYTES;
    const __half* pa = A + (size_t)(m0 + r) * lda + k0;
    cp16(sb + OFF_A + rowoff + (uint32_t)cb * 16, pa + cb * 8);
    cp16(sb + OFF_A + rowoff + (uint32_t)(cb + 1) * 16, pa + (cb + 1) * 8);
}
__device__ __forceinline__ void load_stage_B(
    uint32_t sb, const __half* __restrict__ B, int ldb, int n0, int k0)
{
    int t = threadIdx.x;
    int r = t >> 3, c = t & 7;
    const __half* pb = B + (size_t)(n0 + r) * ldb + k0;
    cp16(sb + OFF_B + (uint32_t)r * ROW_BYTES + (uint32_t)c * 16, pb + c * 8);
}

// ---------------------------------------------------------------------------
// One BK=64 stage. 16 warps in 4(m) x 4(n), warp tile 32x16, acc[2][2][4].
// ---------------------------------------------------------------------------
__device__ __forceinline__ void compute_stage(uint32_t sb, float (&acc)[2][2][4])
{
    int tid = threadIdx.x;
    int lane = tid & 31, wid = tid >> 5;
    int wm = wid >> 2, wn = wid & 3;
    int lr = lane & 15, lc = lane >> 4;
    uint32_t a_base = (uint32_t)(wm * 32 + lr) * ROW_BYTES + (uint32_t)lc * 16;
    uint32_t b_base = (uint32_t)(wn * 16 + lr) * ROW_BYTES + (uint32_t)lc * 16;

    #pragma unroll
    for (int kk = 0; kk < 4; kk++) {
        uint32_t koff = (uint32_t)kk * 32;
        uint32_t a[2][4], b[4];
        #pragma unroll
        for (int mi = 0; mi < 2; mi++)
            ldm_x4(a[mi], sb + OFF_A + a_base + (uint32_t)mi * (16 * ROW_BYTES) + koff);
        ldm_x4(b, sb + OFF_B + b_base + koff);
        #pragma unroll
        for (int mi = 0; mi < 2; mi++) {
            #pragma unroll
            for (int ni = 0; ni < 2; ni++) {
                mma_f16(acc[mi][ni], a[mi], b[ni], b[ni + 2]);
            }
        }
    }
}

// ---------------------------------------------------------------------------
// Group loader: loads stages 2g, 2g+1 (segment chosen per stage).
// ---------------------------------------------------------------------------
__device__ __forceinline__ void load_group(
    uint32_t sbase, int g, int nst1,
    const __half* A1, int lda1, const __half* B1, int ldb1, int kbase1,
    const __half* A2, int lda2, const __half* B2, int ldb2, int kbase2,
    int m0, int n0, bool skip_b0)
{
    uint32_t gb = sbase + (uint32_t)(g % DEPTH_G) * GROUP_BYTES;
    #pragma unroll
    for (int j = 0; j < 2; j++) {
        int s = 2 * g + j;
        uint32_t buf = gb + (uint32_t)j * STAGE_BYTES;
        if (s < nst1) {
            if (!(s == 0 && skip_b0))
                load_stage_B(buf, B1, ldb1, n0, kbase1 + s * BK);
            load_stage_A(buf, A1, lda1, m0, kbase1 + s * BK);
        } else {
            int s2 = s - nst1;
            load_stage_B(buf, B2, ldb2, n0, kbase2 + s2 * BK);
            load_stage_A(buf, A2, lda2, m0, kbase2 + s2 * BK);
        }
    }
}

// Dual-segment grouped pipeline (group = 2 stages, 3 groups circular,
// cp_wait<1> in group units -> 4-stage lookahead, half the barriers).
// Requires K1/BK and (K1+K2)/BK even (true for all call sites).
__device__ void gemm_dual(
    uint32_t sbase,
    const __half* A1, int lda1, const __half* B1, int ldb1, int K1, int kbase1,
    const __half* A2, int lda2, const __half* B2, int ldb2, int K2, int kbase2,
    int m0, int n0, bool prefetched_b0, float (&acc)[2][2][4])
{
    int nst1 = K1 / BK;
    int ng = (nst1 + K2 / BK) / 2;

    #pragma unroll
    for (int p = 0; p < 2; p++) {
        if (p < ng)
            load_group(sbase, p, nst1, A1, lda1, B1, ldb1, kbase1,
                       A2, lda2, B2, ldb2, kbase2, m0, n0, prefetched_b0);
        cp_commit();
    }
    for (int g = 0; g < ng; g++) {
        cp_wait<1>();
        __syncthreads();
        if (g + 2 < ng)
            load_group(sbase, g + 2, nst1, A1, lda1, B1, ldb1, kbase1,
                       A2, lda2, B2, ldb2, kbase2, m0, n0, false);
        cp_commit();
        uint32_t gb = sbase + (uint32_t)(g % DEPTH_G) * GROUP_BYTES;
        compute_stage(gb, acc);
        compute_stage(gb + STAGE_BYTES, acc);
    }
}

// ---------------------------------------------------------------------------
// Epilogue: bias / add / rho, write fp16 state and/or fp32. fold_addm:
// write (addm+addm2) back into addm (c2 fold at t=1).
// ---------------------------------------------------------------------------
__device__ void epilogue(
    float (&acc)[2][2][4], int m0, int n0, int outw,
    const float* __restrict__ bias, float* __restrict__ addm,
    const float* __restrict__ addm2, bool fold_addm, bool do_rho,
    __half* __restrict__ oh, float* __restrict__ of)
{
    int tid = threadIdx.x;
    int lane = tid & 31, wid = tid >> 5;
    int wm = wid >> 2, wn = wid & 3;
    int g = lane >> 2, t = lane & 3;

    #pragma unroll
    for (int mi = 0; mi < 2; mi++) {
        #pragma unroll
        for (int ni = 0; ni < 2; ni++) {
            int nc = n0 + wn * 16 + ni * 8 + 2 * t;
            float bv0 = 0.f, bv1 = 0.f;
            if (bias) { bv0 = bias[nc]; bv1 = bias[nc + 1]; }
            #pragma unroll
            for (int h = 0; h < 2; h++) {
                int mr = m0 + wm * 32 + mi * 16 + g + h * 8;
                float v0 = acc[mi][ni][2 * h + 0] + bv0;
                float v1 = acc[mi][ni][2 * h + 1] + bv1;
                size_t o = (size_t)mr * outw + nc;
                if (addm) {
                    float2 av = *(const float2*)&addm[o];
                    float a0 = av.x, a1 = av.y;
                    if (addm2) {
                        float2 av2 = *(const float2*)&addm2[o];
                        a0 += av2.x; a1 += av2.y;
                        if (fold_addm)
                            *(float2*)&addm[o] = make_float2(a0, a1);
                    }
                    v0 += a0; v1 += a1;
                }
                if (do_rho) {
                    v0 = fminf(fmaxf(v0, 0.f), 1.f);
                    v1 = fminf(fmaxf(v1, 0.f), 1.f);
                }
                if (oh) {
                    __half2 hp;
                    hp.x = __float2half_rn(v0);
                    hp.y = __float2half_rn(v1);
                    *(__half2*)&oh[o] = hp;
                }
                if (of) *(float2*)&of[o] = make_float2(v0, v1);
            }
        }
    }
}

// ---------------------------------------------------------------------------
// Persistent kernel, per-m-half pipelines.
// 144 CTAs: [0,16) G0 2x8   [16,80) G1 2x32   [80,144) G2 2x32
// ---------------------------------------------------------------------------
__global__ void __launch_bounds__(THREADS, 1) ep_steps_persist(
    __half* s0base, __half* s1base, __half* s2base,
    const __half* W0, const __half* W1,
    const __half* W0T, const __half* W1T,
    const float* b0, const float* b1,
    float* c2, const float* c2p, float* c1pbase, float* out)
{
    extern __shared__ char dyn[];
    uint32_t sb = smem_u32(dyn);
    const size_t n0e = (size_t)BATCH * D0;
    const size_t n1e = (size_t)BATCH * D1;
    const size_t n2e = (size_t)BATCH * D2;
    int blk = blockIdx.x;
    int group = (blk < 16) ? 0 : (blk < 80 ? 1 : 2);

    int m0t, n0t;
    if (group == 0) { m0t = (blk >> 3) * BM; n0t = (blk & 7) * BN; }
    else if (group == 1) { int l = blk - 16; m0t = (l >> 5) * BM; n0t = (l & 31) * BN; }
    else { int l = blk - 80; m0t = (l >> 5) * BM; n0t = (l & 31) * BN; }
    int mh = m0t ? 1 : 0;

    for (int t = 1; t <= T_STEPS; t++) {
        int pi = (t - 1) & 1, po = t & 1;
        const __half* i0 = s0base + (size_t)pi * n0e;
        const __half* i1 = s1base + (size_t)pi * n1e;
        const __half* i2 = s2base + (size_t)pi * n2e;
        float* c1p = c1pbase + (size_t)po * n1e;
        bool last = (t == T_STEPS);
        __half *o0 = nullptr, *o1 = nullptr, *o2 = nullptr;
        float *f0 = nullptr, *f1 = nullptr, *f2 = nullptr;
        if (last) {
            f0 = out;
            f1 = out + n0e;
            f2 = out + n0e + n1e;
        } else {
            o0 = s0base + (size_t)po * n0e;
            o1 = s1base + (size_t)po * n1e;
            o2 = s2base + (size_t)po * n2e;
        }

        float acc[2][2][4];
        #pragma unroll
        for (int i = 0; i < 2; i++)
            #pragma unroll
            for (int j = 0; j < 2; j++)
                #pragma unroll
                for (int k = 0; k < 4; k++) acc[i][j][k] = 0.f;

        if (group == 0) {
            // prefetch stage-0 weight tile, then wait for s1(t-1) of own half
            load_stage_B(sb, W0, D1, n0t, 0);
            if (t > 1) wait_flag(&g_done1[mh], (t - 1) * 32);
            gemm_dual(sb, i1, D1, W0, D1, D1, 0,
                      i1, D1, W0, D1, 0, 0, m0t, n0t, true, acc);
            epilogue(acc, m0t, n0t, D0, b0, nullptr, nullptr, false, true, o0, f0);
            if (t < T_STEPS) signal_flag(&g_done0[mh]);
        } else if (group == 1) {
            load_stage_B(sb, W1, D2, n0t, 0);
            if (t > 1) {
                wait_flag(&g_done2[mh], (t - 1) * 32);   // s2 input
                wait_flag(&g_done0[mh], (t - 1) * 8);    // s0 input
            }
            // 32 stages s2@W1^T + 4 stages s0@W0 (k < 256)
            gemm_dual(sb, i2, D2, W1, D2, D2, 0,
                      i0, D0, W0T, D0, 256, 0, m0t, n0t, true, acc);
            wait_flag(&g_part[mh], t * 32);              // G2 partial ready
            epilogue(acc, m0t, n0t, D1, b1, c1p, nullptr, false, true, o1, f1);
            if (t < T_STEPS) signal_flag(&g_done1[mh]);
        } else {
            load_stage_B(sb, W0T, D0, n0t, 256);
            if (t > 1) {
                wait_flag(&g_done1[mh], (t - 1) * 32);   // s1 input + c1p WAR
                wait_flag(&g_done0[mh], (t - 1) * 8);    // s0 input for partial
            }
            // 4-stage split-K partial: s0[k 256:512] @ W0T
            gemm_dual(sb, i0, D0, W0T, D0, 256, 256,
                      i0, D0, W0T, D0, 0, 0, m0t, n0t, true, acc);
            epilogue(acc, m0t, n0t, D1, nullptr, nullptr, nullptr, false, false,
                     nullptr, c1p);
            signal_flag(&g_part[mh]);
            // own 32-stage s2 update
            #pragma unroll
            for (int i = 0; i < 2; i++)
                #pragma unroll
                for (int j = 0; j < 2; j++)
                    #pragma unroll
                    for (int k = 0; k < 4; k++) acc[i][j][k] = 0.f;
            gemm_dual(sb, i1, D1, W1T, D1, D1, 0,
                      i1, D1, W1T, D1, 0, 0, m0t, n0t, false, acc);
            // t==1: fold c2p into c2 so later steps read one buffer
            epilogue(acc, m0t, n0t, D2, nullptr, c2, (t == 1) ? c2p : nullptr,
                     t == 1, true, o2, f2);
            if (t < T_STEPS) signal_flag(&g_done2[mh]);
        }
    }
}

// C2 split-K: 128 CTAs. half 0: c2 = z(K[0,2048)) + b2. half 1: c2p.
__global__ void __launch_bounds__(THREADS, 1) ep_c2_kernel(
    const __half* dh, const __half* W2, const float* b2,
    float* c2, float* c2p)
{
    extern __shared__ char dyn[];
    uint32_t sb = smem_u32(dyn);

    float acc[2][2][4];
    #pragma unroll
    for (int i = 0; i < 2; i++)
        #pragma unroll
        for (int j = 0; j < 2; j++)
            #pragma unroll
            for (int k = 0; k < 4; k++) acc[i][j][k] = 0.f;

    int blk = blockIdx.x;
    int half = blk >> 6;
    int l = blk & 63;
    int m0 = (l >> 5) * BM, n0 = (l & 31) * BN;
    int kbase = half * (DIN / 2);

    gemm_dual(sb, dh, DIN, W2, DIN, DIN / 2, kbase,
              dh, DIN, W2, DIN, 0, 0, m0, n0, false, acc);

    int tid = threadIdx.x;
    int lane = tid & 31, wid = tid >> 5;
    int wm = wid >> 2, wn = wid & 3;
    int g = lane >> 2, t = lane & 3;
    float* dst = half ? c2p : c2;
    #pragma unroll
    for (int mi = 0; mi < 2; mi++) {
        #pragma unroll
        for (int ni = 0; ni < 2; ni++) {
            int nc = n0 + wn * 16 + ni * 8 + 2 * t;
            float bv0 = half ? 0.f : b2[nc];
            float bv1 = half ? 0.f : b2[nc + 1];
            #pragma unroll
            for (int h = 0; h < 2; h++) {
                int mr = m0 + wm * 32 + mi * 16 + g + h * 8;
                float v0 = acc[mi][ni][2 * h + 0] + bv0;
                float v1 = acc[mi][ni][2 * h + 1] + bv1;
                *(float2*)&dst[(size_t)mr * D2 + nc] = make_float2(v0, v1);
            }
        }
    }
}

// ====================== fused conversion kernel ============================
__device__ __forceinline__ void vec4_to_h(const float* x, __half* h, int idx) {
    float4 v = *(const float4*)&x[idx];
    __half2 p0, p1;
    p0.x = __float2half_rn(v.x); p0.y = __float2half_rn(v.y);
    p1.x = __float2half_rn(v.z); p1.y = __float2half_rn(v.w);
    *(__half2*)&h[idx] = p0;
    *(__half2*)&h[idx + 2] = p1;
}

// block ranges (each non-transpose block converts 1024 elems)
#define CB_W1   1024
#define CB_W2   5120
#define CB_DATA 13312
#define CB_S0   14336
#define CB_S1   14464
#define CB_S2   14976
#define CB_W0T  15488
#define CB_W1T  16512
#define CB_TOTAL 20608

__global__ void __launch_bounds__(256) fused_convert(
    const float* __restrict__ W0, const float* __restrict__ W1,
    const float* __restrict__ W2, const float* __restrict__ data,
    const float* __restrict__ s0, const float* __restrict__ s1,
    const float* __restrict__ s2,
    __half* hW0, __half* hW1, __half* hW0T, __half* hW1T,
    __half* hW2, __half* hd,
    __half* hs0, __half* hs1, __half* hs2)
{
    __shared__ float tile[32][33];
    int b = blockIdx.x, tid = threadIdx.x;
    if (b == 0 && tid < 2) {
        g_done0[tid] = 0; g_done1[tid] = 0; g_done2[tid] = 0; g_part[tid] = 0;
    }

    if (b < CB_W1) {
        vec4_to_h(W0, hW0, (b * 256 + tid) * 4);
    } else if (b < CB_W2) {
        vec4_to_h(W1, hW1, ((b - CB_W1) * 256 + tid) * 4);
    } else if (b < CB_DATA) {
        vec4_to_h(W2, hW2, ((b - CB_W2) * 256 + tid) * 4);
    } else if (b < CB_S0) {
        vec4_to_h(data, hd, ((b - CB_DATA) * 256 + tid) * 4);
    } else if (b < CB_S1) {
        vec4_to_h(s0, hs0, ((b - CB_S0) * 256 + tid) * 4);
    } else if (b < CB_S2) {
        vec4_to_h(s1, hs1, ((b - CB_S1) * 256 + tid) * 4);
    } else if (b < CB_W0T) {
        vec4_to_h(s2, hs2, ((b - CB_S2) * 256 + tid) * 4);
    } else if (b < CB_W1T) {
        int local = b - CB_W0T;
        int bx = local % (D1 / 32), by = local / (D1 / 32);
        int tx = tid & 31, ty = tid >> 5;
        int c0 = bx * 32, r0 = by * 32;
        #pragma unroll
        for (int k = 0; k < 4; k++)
            tile[ty + 8 * k][tx] = W0[(size_t)(r0 + ty + 8 * k) * D1 + c0 + tx];
        __syncthreads();
        #pragma unroll
        for (int k = 0; k < 4; k++) {
            size_t o = (size_t)(c0 + ty + 8 * k) * D0 + r0 + tx;
            hW0T[o] = __float2half_rn(tile[tx][ty + 8 * k]);
        }
    } else {
        int local = b - CB_W1T;
        int bx = local % (D2 / 32), by = local / (D2 / 32);
        int tx = tid & 31, ty = tid >> 5;
        int c0 = bx * 32, r0 = by * 32;
        #pragma unroll
        for (int k = 0; k < 4; k++)
            tile[ty + 8 * k][tx] = W1[(size_t)(r0 + ty + 8 * k) * D2 + c0 + tx];
        __syncthreads();
        #pragma unroll
        for (int k = 0; k < 4; k++) {
            size_t o = (size_t)(c0 + ty + 8 * k) * D1 + r0 + tx;
            hW1T[o] = __float2half_rn(tile[tx][ty + 8 * k]);
        }
    }
}

// ------------------------------- host side ---------------------------------
static inline void* sym(const void* s) {
    void* p = nullptr;
    cudaGetSymbolAddress(&p, s);
    return p;
}

extern "C" void kernel_launch(void* const* d_in, const int* in_sizes, int n_in,
                              void* d_out, int out_size)
{
    const float* data = (const float*)d_in[0];
    const float* in_s0 = (const float*)d_in[1];
    const float* in_s1 = (const float*)d_in[2];
    const float* in_s2 = (const float*)d_in[3];
    const float* W0 = (const float*)d_in[4];
    const float* b0 = (const float*)d_in[5];
    const float* W1 = (const float*)d_in[6];
    const float* b1 = (const float*)d_in[7];
    const float* W2 = (const float*)d_in[8];
    const float* b2 = (const float*)d_in[9];
    float* out = (float*)d_out;

    cudaFuncSetAttribute(ep_steps_persist, cudaFuncAttributeMaxDynamicSharedMemorySize, DSMEM_BYTES);
    cudaFuncSetAttribute(ep_c2_kernel,     cudaFuncAttributeMaxDynamicSharedMemorySize, DSMEM_BYTES);

    __half *hW0 = (__half*)sym(g_hW0), *hW1 = (__half*)sym(g_hW1);
    __half *hW0T = (__half*)sym(g_hW0T), *hW1T = (__half*)sym(g_hW1T);
    __half *hW2 = (__half*)sym(g_hW2), *hd = (__half*)sym(g_hd);
    __half *hs0 = (__half*)sym(g_hs0);
    __half *hs1 = (__half*)sym(g_hs1);
    __half *hs2 = (__half*)sym(g_hs2);
    float* c2 = (float*)sym(g_c2);
    float* c2p = (float*)sym(g_c2p);
    float* c1p = (float*)sym(g_c1p);

    fused_convert<<<CB_TOTAL, 256>>>(
        W0, W1, W2, data, in_s0, in_s1, in_s2,
        hW0, hW1, hW0T, hW1T, hW2, hd, hs0, hs1, hs2);

    ep_c2_kernel<<<128, THREADS, DSMEM_BYTES>>>(hd, hW2, b2, c2, c2p);

    ep_steps_persist<<<144, THREADS, DSMEM_BYTES>>>(
        hs0, hs1, hs2,
        hW0, hW1, hW0T, hW1T,
        b0, b1, c2, c2p, c1p, out);
}